// round 4
// baseline (speedup 1.0000x reference)
#include <cuda_runtime.h>
#include <cstddef>

// B=128, D=1024. d_in[0]=mu (131072 f32), d_in[1]=Sigma (128*1024*1024 f32)
// d_out = [mu_out 131072 f32 | Sigma_out 134217728 f32]

static constexpr int B = 128;
static constexpr int D = 1024;
static constexpr int ROWS = 8;   // Sigma rows per block

// One block = 8 consecutive rows of Sigma (always within one batch b since
// 1024 % 8 == 0). 256 threads; thread t owns columns [4t, 4t+4) of all 8 rows:
//   - two float4 loads give the 8 row-masks (mu[8*blk .. 8*blk+7])
//   - one float4 load of the mu row gives the column mask, reused 8x
//   - 8 independent Sigma float4 loads (MLP=8), predicated off per-row mask
// Thread 0 writes the relu'd mu_out for the block's 8 rows.
__global__ __launch_bounds__(256) void rvrelu_fused8_kernel(
    const float4* __restrict__ Sigma,
    const float*  __restrict__ mu,
    float4* __restrict__ Sigma_out,
    float4* __restrict__ mu_out4) {

    const int blk  = blockIdx.x;         // 0 .. 16383
    const int row0 = blk * ROWS;         // first of 8 rows
    const int b    = row0 >> 10;         // batch index
    const int t    = threadIdx.x;        // 0..255

    // 8 row masks in two aligned 16B loads (L2-hot)
    const float4 miA = __ldg(reinterpret_cast<const float4*>(mu) + 2 * blk);
    const float4 miB = __ldg(reinterpret_cast<const float4*>(mu) + 2 * blk + 1);

    // fused mu_out: two relu'd float4 stores per block
    if (t == 0) {
        float4 rA, rB;
        rA.x = miA.x > 0.0f ? miA.x : 0.0f;
        rA.y = miA.y > 0.0f ? miA.y : 0.0f;
        rA.z = miA.z > 0.0f ? miA.z : 0.0f;
        rA.w = miA.w > 0.0f ? miA.w : 0.0f;
        rB.x = miB.x > 0.0f ? miB.x : 0.0f;
        rB.y = miB.y > 0.0f ? miB.y : 0.0f;
        rB.z = miB.z > 0.0f ? miB.z : 0.0f;
        rB.w = miB.w > 0.0f ? miB.w : 0.0f;
        mu_out4[2 * blk]     = rA;
        mu_out4[2 * blk + 1] = rB;
    }

    // column mask: mu[b, 4t..4t+3], shared by all 8 rows
    const float4 mrow =
        __ldg(reinterpret_cast<const float4*>(mu + (size_t)b * D) + t);

    const float mis[ROWS] = {miA.x, miA.y, miA.z, miA.w,
                             miB.x, miB.y, miB.z, miB.w};

    const size_t base = (size_t)row0 * (D / 4) + t;   // float4 index

    // Phase 1: issue all 8 independent Sigma loads (predicated) -> MLP=8
    float4 v[ROWS];
#pragma unroll
    for (int r = 0; r < ROWS; r++) {
        if (mis[r] > 0.0f) {
            v[r] = __ldg(Sigma + base + (size_t)r * (D / 4));
        } else {
            v[r] = make_float4(0.0f, 0.0f, 0.0f, 0.0f);
        }
    }

    // Phase 2: apply column mask and store
#pragma unroll
    for (int r = 0; r < ROWS; r++) {
        float4 o = v[r];
        o.x = mrow.x > 0.0f ? o.x : 0.0f;
        o.y = mrow.y > 0.0f ? o.y : 0.0f;
        o.z = mrow.z > 0.0f ? o.z : 0.0f;
        o.w = mrow.w > 0.0f ? o.w : 0.0f;
        Sigma_out[base + (size_t)r * (D / 4)] = o;
    }
}

extern "C" void kernel_launch(void* const* d_in, const int* in_sizes, int n_in,
                              void* d_out, int out_size) {
    const float* mu    = (const float*)d_in[0];
    const float* Sigma = (const float*)d_in[1];

    float4* mu_out4   = (float4*)d_out;
    float4* Sigma_out = (float4*)((float*)d_out + (size_t)B * D);

    // 16384 blocks x 256 threads; 8 Sigma rows per block
    rvrelu_fused8_kernel<<<(B * D) / ROWS, 256>>>(
        (const float4*)Sigma, mu, Sigma_out, mu_out4);
}

// round 5
// speedup vs baseline: 1.0129x; 1.0129x over previous
#include <cuda_runtime.h>
#include <cstddef>

// B=128, D=1024. d_in[0]=mu (131072 f32), d_in[1]=Sigma (128*1024*1024 f32)
// d_out = [mu_out 131072 f32 | Sigma_out 134217728 f32]

static constexpr int B = 128;
static constexpr int D = 1024;
static constexpr int ROWS = 4;   // Sigma rows per block (R2 config, best so far)

// One block = 4 consecutive rows of Sigma. 256 threads; thread t owns columns
// [4t, 4t+4) of all 4 rows. All bulk traffic uses streaming (evict-first)
// cache hints: Sigma is read once and never reused, Sigma_out is written once
// and never re-read -> keep both out of L2's retained set to cut
// allocate/writeback churn on the 768 MB stream.
__global__ __launch_bounds__(256) void rvrelu_fused_cs_kernel(
    const float4* __restrict__ Sigma,
    const float*  __restrict__ mu,
    float4* __restrict__ Sigma_out,
    float4* __restrict__ mu_out4) {

    const int blk  = blockIdx.x;        // 0 .. 32767
    const int row0 = blk << 2;          // first of 4 rows
    const int b    = row0 >> 10;        // batch index
    const int t    = threadIdx.x;       // 0..255

    // 4 row masks in one aligned 16B load (L2-hot, default policy: reused)
    const float4 mi4 = __ldg(reinterpret_cast<const float4*>(mu) + blk);

    // fused mu_out: one relu'd float4 store per block
    if (t == 0) {
        float4 r;
        r.x = mi4.x > 0.0f ? mi4.x : 0.0f;
        r.y = mi4.y > 0.0f ? mi4.y : 0.0f;
        r.z = mi4.z > 0.0f ? mi4.z : 0.0f;
        r.w = mi4.w > 0.0f ? mi4.w : 0.0f;
        __stcs(mu_out4 + blk, r);
    }

    // column mask: mu[b, 4t..4t+3], shared by all 4 rows (L2-hot)
    const float4 mrow =
        __ldg(reinterpret_cast<const float4*>(mu + (size_t)b * D) + t);

    const float mis[ROWS] = {mi4.x, mi4.y, mi4.z, mi4.w};
    const size_t base = (size_t)row0 * (D / 4) + t;   // float4 index

    // Phase 1: issue all 4 independent Sigma loads (predicated, streaming)
    float4 v[ROWS];
#pragma unroll
    for (int r = 0; r < ROWS; r++) {
        if (mis[r] > 0.0f) {
            v[r] = __ldcs(Sigma + base + (size_t)r * (D / 4));
        } else {
            v[r] = make_float4(0.0f, 0.0f, 0.0f, 0.0f);
        }
    }

    // Phase 2: apply column mask and store (streaming)
#pragma unroll
    for (int r = 0; r < ROWS; r++) {
        float4 o = v[r];
        o.x = mrow.x > 0.0f ? o.x : 0.0f;
        o.y = mrow.y > 0.0f ? o.y : 0.0f;
        o.z = mrow.z > 0.0f ? o.z : 0.0f;
        o.w = mrow.w > 0.0f ? o.w : 0.0f;
        __stcs(Sigma_out + base + (size_t)r * (D / 4), o);
    }
}

extern "C" void kernel_launch(void* const* d_in, const int* in_sizes, int n_in,
                              void* d_out, int out_size) {
    const float* mu    = (const float*)d_in[0];
    const float* Sigma = (const float*)d_in[1];

    float4* mu_out4   = (float4*)d_out;
    float4* Sigma_out = (float4*)((float*)d_out + (size_t)B * D);

    // 32768 blocks x 256 threads; 4 Sigma rows per block
    rvrelu_fused_cs_kernel<<<(B * D) / ROWS, 256>>>(
        (const float4*)Sigma, mu, Sigma_out, mu_out4);
}